// round 15
// baseline (speedup 1.0000x reference)
#include <cuda_runtime.h>
#include <cstdint>
#include <cstddef>

#define BB 64
#define SS 2048
#define DIN 512
#define HH 1024
#define SPLITS 8                       // tiles per batch; 512 tiles total
#define NTILES (BB * SPLITS)
#define ROWS_PER_TILE (SS / SPLITS)    // 256
#define NWARP 16
#define RING_DEPTH 3
#define KSPLIT 32                      // gemm k-chunks
#define KC 16
#define HC 64

#define NEG_INF __int_as_float(0xff800000)

// ---------------- scratch (no allocations allowed) ----------------
__device__ __align__(16) float g_x[BB * HH];            // inp@W + b
__device__ __align__(16) float g_xpart[KSPLIT * BB * HH];
__device__ unsigned char  g_mask[BB * SS];              // canonical mask (1 = masked)
__device__ float          g_score[BB * SS];             // raw scores (-inf where masked)
__device__ __align__(16) float g_acc[NTILES * HH];      // tile partial weighted sums
__device__ float          g_l[NTILES];                  // tile partial sum-of-exp
__device__ unsigned       g_ticket;                     // persistent work queue
__device__ unsigned       g_bdone[BB];                  // per-batch tile completion

// ---------------- helpers ----------------
__device__ __forceinline__ float tanh_fast(float x) {
    float y;
    asm("tanh.approx.f32 %0, %1;" : "=f"(y) : "f"(x));
    return y;
}

// ---------------- kernel 0: gemm partials (512 CTAs) + mask (64 CTAs) -------
__global__ __launch_bounds__(256) void prologue_kernel(const float* __restrict__ inp,
                                                       const float* __restrict__ Wm,
                                                       const void*  __restrict__ mraw) {
    __shared__ float Ws[KC][HC];   // 4 KB
    __shared__ float Is[KC][BB];   // 4 KB (k-major)
    int t   = threadIdx.x;
    int blk = blockIdx.x;

    if (blk < 512) {                               // ---- GEMM partials ----
        int kc = blk >> 4, hcb = blk & 15;
        int k0 = kc * KC, h0 = hcb * HC;

        {   // Ws: 16x64 = 256 float4, one per thread
            int k = t >> 4, hj = t & 15;
            *(float4*)&Ws[k][hj * 4] =
                *(const float4*)&Wm[(size_t)(k0 + k) * HH + h0 + hj * 4];
        }
        {   // Is: 64b x 16k = 256 float4, one per thread
            int b = t >> 2, j = t & 3;
            float4 p = *(const float4*)&inp[b * DIN + k0 + j * 4];
            Is[j * 4 + 0][b] = p.x;
            Is[j * 4 + 1][b] = p.y;
            Is[j * 4 + 2][b] = p.z;
            Is[j * 4 + 3][b] = p.w;
        }
        __syncthreads();

        int ty = t >> 4, tx = t & 15;          // 4 batches x 4 cols / thread
        float4 a0 = {0,0,0,0}, a1 = {0,0,0,0}, a2 = {0,0,0,0}, a3 = {0,0,0,0};
#pragma unroll
        for (int k = 0; k < KC; k++) {
            float4 ib = *(const float4*)&Is[k][ty * 4];
            float4 wv = *(const float4*)&Ws[k][tx * 4];
            a0.x = fmaf(ib.x, wv.x, a0.x); a0.y = fmaf(ib.x, wv.y, a0.y);
            a0.z = fmaf(ib.x, wv.z, a0.z); a0.w = fmaf(ib.x, wv.w, a0.w);
            a1.x = fmaf(ib.y, wv.x, a1.x); a1.y = fmaf(ib.y, wv.y, a1.y);
            a1.z = fmaf(ib.y, wv.z, a1.z); a1.w = fmaf(ib.y, wv.w, a1.w);
            a2.x = fmaf(ib.z, wv.x, a2.x); a2.y = fmaf(ib.z, wv.y, a2.y);
            a2.z = fmaf(ib.z, wv.z, a2.z); a2.w = fmaf(ib.z, wv.w, a2.w);
            a3.x = fmaf(ib.w, wv.x, a3.x); a3.y = fmaf(ib.w, wv.y, a3.y);
            a3.z = fmaf(ib.w, wv.z, a3.z); a3.w = fmaf(ib.w, wv.w, a3.w);
        }
        float* outb = g_xpart + (size_t)kc * (BB * HH) + h0 + tx * 4;
        *(float4*)&outb[(ty * 4 + 0) * HH] = a0;
        *(float4*)&outb[(ty * 4 + 1) * HH] = a1;
        *(float4*)&outb[(ty * 4 + 2) * HH] = a2;
        *(float4*)&outb[(ty * 4 + 3) * HH] = a3;
    } else {                                    // ---- mask canonicalize ----
        const unsigned* wds = (const unsigned*)mraw;
        int notInt = 0, notFloat = 0;
        for (int i = t; i < 1024; i += 256) {
            unsigned x = wds[i];
            notInt   |= (x > 1u);
            notFloat |= (x != 0u && x != 0x3F800000u);
        }
        notInt   = __syncthreads_or(notInt);
        notFloat = __syncthreads_or(notFloat);
        int mode = notInt ? (notFloat ? 2 : 1) : 0;  // 0:int32 1:float32 2:bytes

        int base = (blk - 512) * 2048;
        for (int i = base + t; i < base + 2048; i += 256) {
            unsigned char v;
            if (mode == 0)      v = (((const int*)mraw)[i] != 0);
            else if (mode == 1) v = (((const float*)mraw)[i] != 0.0f);
            else                v = (((const unsigned char*)mraw)[i] != 0);
            g_mask[i] = v;
        }
    }
}

// ---------------- kernel 1: reduce gemm partials + bias, reset counters -----
__global__ __launch_bounds__(128) void xreduce_kernel(const float* __restrict__ bias) {
    int i = blockIdx.x * 128 + threadIdx.x;     // float4 index, 16384 total
    if (i == 0) g_ticket = 0;
    if (i < BB) g_bdone[i] = 0;
    float4 s = *(const float4*)&bias[(i & 255) * 4];
    const float4* xp = (const float4*)g_xpart;
#pragma unroll
    for (int kc = 0; kc < KSPLIT; kc++) {
        float4 p = xp[kc * (BB * HH / 4) + i];
        s.x += p.x; s.y += p.y; s.z += p.z; s.w += p.w;
    }
    ((float4*)g_x)[i] = s;
}

// ---------------- kernel 2: fused scores+exp-sum+weighted sum+finalize ------
__device__ __forceinline__ void issue_row(const float* cb, int k, int n,
                                          unsigned slot_u32, int ln,
                                          const int* s_idx) {
    if (k < n) {
        const float* src = cb + (size_t)s_idx[k] * HH + ln * 4;
        unsigned dst = slot_u32 + ln * 16;
#pragma unroll
        for (int i = 0; i < 8; i++)
            asm volatile("cp.async.cg.shared.global [%0], [%1], 16;"
                         :: "r"(dst + i * 512), "l"(src + i * 128) : "memory");
    }
    asm volatile("cp.async.commit_group;" ::: "memory");
}

__global__ __launch_bounds__(512, 1) void pass1_kernel(const float* __restrict__ ctx,
                                                       const float* __restrict__ v,
                                                       float* __restrict__ out_applied,
                                                       float* __restrict__ out_w) {
    extern __shared__ float dsm[];
    float* xs   = dsm;                 // HH floats
    float* ring = dsm + HH;            // NWARP * RING_DEPTH * HH floats

    __shared__ int      s_idx[ROWS_PER_TILE];
    __shared__ int      s_wcnt[8];
    __shared__ float    s_l[NWARP];
    __shared__ unsigned s_tile;
    __shared__ int      s_last;

    int t  = threadIdx.x;
    int w  = t >> 5;
    int ln = t & 31;

    float4 vv[8];
    const float4* vr = (const float4*)v;
#pragma unroll
    for (int j = 0; j < 8; j++) vv[j] = __ldg(&vr[j * 32 + ln]);

    float* myring = ring + w * (RING_DEPTH * HH);
    unsigned ring_u32 = (unsigned)__cvta_generic_to_shared(myring);

    for (;;) {
        if (t == 0) s_tile = atomicAdd(&g_ticket, 1u);
        __syncthreads();               // also orders prior tile's smem reuse
        unsigned tile = s_tile;
        if (tile >= NTILES) break;

        int b  = tile >> 3;            // SPLITS = 8
        int sp = tile & (SPLITS - 1);
        int rowbase = b * SS + sp * ROWS_PER_TILE;

        xs[t]       = g_x[b * HH + t];
        xs[t + 512] = g_x[b * HH + 512 + t];

        // ---- compact unmasked row indices (deterministic order) ----
        unsigned char mk = 1;
        if (t < ROWS_PER_TILE) mk = g_mask[rowbase + t];
        unsigned bits = __ballot_sync(0xffffffffu, mk == 0);
        if (t < ROWS_PER_TILE && mk) g_score[rowbase + t] = NEG_INF;
        if (w < 8 && ln == 0) s_wcnt[w] = __popc(bits);
        __syncthreads();
        int n = 0;
#pragma unroll
        for (int i = 0; i < 8; i++) n += s_wcnt[i];
        if (t < ROWS_PER_TILE && !mk) {
            int basew = 0;
#pragma unroll
            for (int i = 0; i < 8; i++) if (i < w) basew += s_wcnt[i];
            s_idx[basew + __popc(bits & ((1u << ln) - 1u))] = t;
        }
        __syncthreads();

        // ---- per-warp row loop over compacted list ----
        float4 acc[8];
#pragma unroll
        for (int j = 0; j < 8; j++) acc[j] = make_float4(0.f, 0.f, 0.f, 0.f);
        float l = 0.f;

        const float* cb = ctx + (size_t)rowbase * HH;
        issue_row(cb, w,             n, ring_u32,          ln, s_idx);
        issue_row(cb, w + NWARP,     n, ring_u32 + HH * 4, ln, s_idx);
        issue_row(cb, w + 2 * NWARP, n, ring_u32 + HH * 8, ln, s_idx);
        int slot = 0;
        for (int k = w; k < n; k += NWARP) {
            asm volatile("cp.async.wait_group 2;" ::: "memory");
            const float* sp_ = myring + slot * HH;

            float part = 0.f;
#pragma unroll
            for (int j = 0; j < 8; j++) {
                float4 c  = *(const float4*)&sp_[j * 128 + ln * 4];
                float4 xj = *(const float4*)&xs[j * 128 + ln * 4];
                float4 vg = vv[j];
                part = fmaf(tanh_fast(xj.x + c.x), vg.x, part);
                part = fmaf(tanh_fast(xj.y + c.y), vg.y, part);
                part = fmaf(tanh_fast(xj.z + c.z), vg.z, part);
                part = fmaf(tanh_fast(xj.w + c.w), vg.w, part);
            }
#pragma unroll
            for (int off = 16; off; off >>= 1)
                part += __shfl_xor_sync(0xffffffffu, part, off);

            if (ln == 0) g_score[rowbase + s_idx[k]] = part;
            float p = __expf(part);    // fixed reference M=0: |score| < 40
            l += p;
#pragma unroll
            for (int j = 0; j < 8; j++) {          // re-read row (LDS, no spill)
                float4 c = *(const float4*)&sp_[j * 128 + ln * 4];
                acc[j].x = fmaf(c.x, p, acc[j].x);
                acc[j].y = fmaf(c.y, p, acc[j].y);
                acc[j].z = fmaf(c.z, p, acc[j].z);
                acc[j].w = fmaf(c.w, p, acc[j].w);
            }
            issue_row(cb, k + 3 * NWARP, n, ring_u32 + slot * HH * 4, ln, s_idx);
            slot = (slot == RING_DEPTH - 1) ? 0 : slot + 1;
        }
        asm volatile("cp.async.wait_group 0;" ::: "memory");

        // ---- CTA combine: overlay acc onto ring smem, tree-reduce ----
        if (ln == 0) s_l[w] = l;
        __syncthreads();
        float* sout = ring;
#pragma unroll
        for (int j = 0; j < 8; j++)
            *(float4*)&sout[w * HH + j * 128 + ln * 4] = acc[j];
        __syncthreads();

        float L = 0.f;
#pragma unroll
        for (int i = 0; i < NWARP; i++) L += s_l[i];
        float sum0 = 0.f, sum1 = 0.f;
#pragma unroll
        for (int i = 0; i < NWARP; i++) {
            sum0 += sout[i * HH + t];
            sum1 += sout[i * HH + t + 512];
        }
        g_acc[(size_t)tile * HH + t]       = sum0;
        g_acc[(size_t)tile * HH + t + 512] = sum1;
        if (t == 0) g_l[tile] = L;

        // ---- last tile of this batch? finalize the batch here ----
        __threadfence();
        if (t == 0) {
            unsigned old = atomicAdd(&g_bdone[b], 1u);
            s_last = (old == SPLITS - 1);
        }
        __syncthreads();
        if (s_last) {
            float Lb = 0.f;
#pragma unroll
            for (int i = 0; i < SPLITS; i++) Lb += __ldcg(&g_l[b * SPLITS + i]);
            float invL = 1.0f / Lb;
#pragma unroll
            for (int r = 0; r < 2; r++) {
                int h = t + r * 512;
                float s = 0.f;
#pragma unroll
                for (int i = 0; i < SPLITS; i++)
                    s += __ldcg(&g_acc[(size_t)(b * SPLITS + i) * HH + h]);
                out_applied[b * HH + h] = s * invL;
            }
#pragma unroll
            for (int r = 0; r < 4; r++) {
                int si = t + r * 512;
                float sc = __ldcg(&g_score[b * SS + si]);  // -inf masked -> 0
                out_w[b * SS + si] = __expf(sc) * invL;
            }
        }
        // top-of-loop __syncthreads orders smem reuse for the next tile
    }
}

// ---------------- launch ----------------
extern "C" void kernel_launch(void* const* d_in, const int* in_sizes, int n_in,
                              void* d_out, int out_size) {
    const float* inp  = (const float*)d_in[0];
    // d_in[1] = hidden (unused by the reference computation)
    const float* ctx  = (const float*)d_in[2];
    const void*  mask = d_in[3];
    const float* Wm   = (const float*)d_in[4];
    const float* bias = (const float*)d_in[5];
    const float* v    = (const float*)d_in[6];
    float* out = (float*)d_out;

    const int dyn_smem = (HH + NWARP * RING_DEPTH * HH) * (int)sizeof(float); // 200704
    cudaFuncSetAttribute(pass1_kernel,
                         cudaFuncAttributeMaxDynamicSharedMemorySize, dyn_smem);

    prologue_kernel<<<576, 256>>>(inp, Wm, mask);
    xreduce_kernel<<<128, 128>>>(bias);
    pass1_kernel<<<152, 512, dyn_smem>>>(ctx, v, out, out + BB * HH);
}